// round 7
// baseline (speedup 1.0000x reference)
#include <cuda_runtime.h>

// ---------------------------------------------------------------------------
// LiftedStructureLoss  (N=8192, D=512, 128 classes)
//   sim = X X^T  (X rows are L2-normalized, fp32)
//   pos_sum[i] = sum_j [t_i==t_j && sim<1] exp(1 - sim_ij)
//   neg_sum[i] = sum_j [t_i!=t_j]          exp(sim_ij)
//   loss = mean_i( log pos_sum + log neg_sum )   (rows with no negs skipped)
//   prec = fraction of rows with no negatives
//   mean_pos_sim / mean_neg_sim: masked means of the LAST row of sim
//
// NOTE: targets are int32 (JAX x64-disabled downcasts int64 -> int32).
// Reading them as int64 was the Round-4 bug (quantitatively confirmed:
// predicted corrupted-label loss 15.57 vs ref 14.17 -> rel 0.0988 ~= measured
// 0.0994).
//
// Strategy: symmetric tiled fp32 GEMM over upper-triangular 128x128 tiles,
// fused exp epilogue accumulating into both row and column sums.
// ---------------------------------------------------------------------------

#define NROWS 8192
#define DIM   512
#define BM    128
#define BN    128
#define BK    16
#define NTHR  256
#define LDA   132   // padded smem leading dim (16B-aligned, bank-conflict-free)

__device__ float g_pos[NROWS];
__device__ float g_neg[NROWS];
__device__ float g_last[4];   // [0]=pos_sim_sum [1]=neg_sim_sum [2]=pos_cnt [3]=neg_cnt
__device__ float g_red[2];    // [0]=loss_sum    [1]=skipped_row_count

// ---------------------------------------------------------------------------
__global__ void zero_kernel() {
    int i = blockIdx.x * blockDim.x + threadIdx.x;
    if (i < NROWS) { g_pos[i] = 0.f; g_neg[i] = 0.f; }
    if (i < 4) g_last[i] = 0.f;
    if (i < 2) g_red[i]  = 0.f;
}

// ---------------------------------------------------------------------------
// Main fused GEMM + masked-exp epilogue over upper-triangular tiles.
// ---------------------------------------------------------------------------
__global__ __launch_bounds__(NTHR, 2)
void sim_kernel(const float* __restrict__ X, const int* __restrict__ T) {
    const int bi = blockIdx.y;
    const int bj = blockIdx.x;
    if (bj < bi) return;                       // upper triangle (incl. diagonal)

    __shared__ float As[BK][LDA];
    __shared__ float Bs[BK][LDA];
    __shared__ int   tr[BM], tc[BN];
    __shared__ float sPR[BM], sNR[BM], sPC[BN], sNC[BN];

    const int tid = threadIdx.x;
    if (tid < BM) {
        tr[tid]  = T[bi * BM + tid];
        tc[tid]  = T[bj * BN + tid];
        sPR[tid] = 0.f; sNR[tid] = 0.f; sPC[tid] = 0.f; sNC[tid] = 0.f;
    }

    const int tx = tid & 15;     // column group (8 cols each)
    const int ty = tid >> 4;     // row group    (8 rows each)

    float acc[8][8];
#pragma unroll
    for (int q = 0; q < 8; q++)
#pragma unroll
        for (int p = 0; p < 8; p++) acc[q][p] = 0.f;

    const float* Abase = X + (size_t)bi * BM * DIM;
    const float* Bbase = X + (size_t)bj * BN * DIM;
    const int s0 = tid * 2;      // two consecutive float4 slots out of 512

    for (int k0 = 0; k0 < DIM; k0 += BK) {
        __syncthreads();
#pragma unroll
        for (int u = 0; u < 2; u++) {
            const int s = s0 + u;
            const int r = s >> 2;
            const int c = (s & 3) * 4;
            float4 va = *(const float4*)(Abase + (size_t)r * DIM + k0 + c);
            As[c + 0][r] = va.x; As[c + 1][r] = va.y;
            As[c + 2][r] = va.z; As[c + 3][r] = va.w;
            float4 vb = *(const float4*)(Bbase + (size_t)r * DIM + k0 + c);
            Bs[c + 0][r] = vb.x; Bs[c + 1][r] = vb.y;
            Bs[c + 2][r] = vb.z; Bs[c + 3][r] = vb.w;
        }
        __syncthreads();

#pragma unroll
        for (int k = 0; k < BK; k++) {
            float a[8], b[8];
            *(float4*)&a[0] = *(const float4*)&As[k][ty * 8];
            *(float4*)&a[4] = *(const float4*)&As[k][ty * 8 + 4];
            *(float4*)&b[0] = *(const float4*)&Bs[k][tx * 8];
            *(float4*)&b[4] = *(const float4*)&Bs[k][tx * 8 + 4];
#pragma unroll
            for (int q = 0; q < 8; q++)
#pragma unroll
                for (int p = 0; p < 8; p++)
                    acc[q][p] = fmaf(a[q], b[p], acc[q][p]);
        }
    }

    // ---- epilogue: masked exp, accumulate row sums (and col sums if off-diag)
    const bool offdiag = (bi != bj);
    float cP[8], cN[8];
#pragma unroll
    for (int p = 0; p < 8; p++) { cP[p] = 0.f; cN[p] = 0.f; }

#pragma unroll
    for (int q = 0; q < 8; q++) {
        const int rm = ty * 8 + q;
        const int tRow = tr[rm];
        float rP = 0.f, rN = 0.f;
#pragma unroll
        for (int p = 0; p < 8; p++) {
            const int cn = tx * 8 + p;
            const float s = acc[q][p];
            if (tRow == tc[cn]) {
                if (s < 1.0f) {                 // drops (most) self-sims, like ref
                    const float e = __expf(1.0f - s);
                    rP += e; cP[p] += e;
                }
            } else {
                const float e = __expf(s);
                rN += e; cN[p] += e;
            }
        }
        atomicAdd(&sPR[rm], rP);
        atomicAdd(&sNR[rm], rN);
    }
    if (offdiag) {
#pragma unroll
        for (int p = 0; p < 8; p++) {
            atomicAdd(&sPC[tx * 8 + p], cP[p]);
            atomicAdd(&sNC[tx * 8 + p], cN[p]);
        }
    }
    __syncthreads();

    if (tid < BM) {
        atomicAdd(&g_pos[bi * BM + tid], sPR[tid]);
        atomicAdd(&g_neg[bi * BM + tid], sNR[tid]);
        if (offdiag) {
            atomicAdd(&g_pos[bj * BN + tid], sPC[tid]);
            atomicAdd(&g_neg[bj * BN + tid], sNC[tid]);
        }
    }
}

// ---------------------------------------------------------------------------
// Last-row statistics in plain fp32 (precision-critical: mean_pos_sim depends
// on whether sim[last,last] < 1.0; use 4-lane split accumulation to keep the
// summation noise comparable to the reference's vectorized sum).
// ---------------------------------------------------------------------------
__global__ void lastrow_kernel(const float* __restrict__ X,
                               const int* __restrict__ T) {
    __shared__ float xl[DIM];
    const int tid = threadIdx.x;
    for (int i = tid; i < DIM; i += blockDim.x)
        xl[i] = X[(size_t)(NROWS - 1) * DIM + i];
    __syncthreads();

    const int j = blockIdx.x * blockDim.x + tid;
    if (j >= NROWS) return;

    const int tl = T[NROWS - 1];
    const float4* xr = (const float4*)(X + (size_t)j * DIM);
    const float4* xs = (const float4*)xl;
    float a0 = 0.f, a1 = 0.f, a2 = 0.f, a3 = 0.f;
#pragma unroll 8
    for (int k = 0; k < DIM / 4; k++) {
        const float4 v = xr[k];
        const float4 w = xs[k];
        a0 = fmaf(v.x, w.x, a0);
        a1 = fmaf(v.y, w.y, a1);
        a2 = fmaf(v.z, w.z, a2);
        a3 = fmaf(v.w, w.w, a3);
    }
    const float s = (a0 + a1) + (a2 + a3);

    if (T[j] == tl) {
        if (s < 1.0f) {
            atomicAdd(&g_last[0], s);
            atomicAdd(&g_last[2], 1.f);
        }
    } else {
        atomicAdd(&g_last[1], s);
        atomicAdd(&g_last[3], 1.f);
    }
}

// ---------------------------------------------------------------------------
__global__ void reduce_kernel() {
    const int i = blockIdx.x * blockDim.x + threadIdx.x;
    if (i >= NROWS) return;
    const float ns = g_neg[i];
    if (ns > 0.f) {
        atomicAdd(&g_red[0], logf(g_pos[i]) + logf(ns));
    } else {
        atomicAdd(&g_red[1], 1.f);
    }
}

__global__ void write_kernel(float* __restrict__ out) {
    if (threadIdx.x == 0) {
        out[0] = g_red[0] / (float)NROWS;   // loss
        out[1] = g_red[1] / (float)NROWS;   // prec (fraction of skipped rows)
        out[2] = g_last[0] / g_last[2];     // mean_pos_sim (last row)
        out[3] = g_last[1] / g_last[3];     // mean_neg_sim (last row)
    }
}

// ---------------------------------------------------------------------------
extern "C" void kernel_launch(void* const* d_in, const int* in_sizes, int n_in,
                              void* d_out, int out_size) {
    const float* X   = (const float*)d_in[0];
    const int*   T   = (const int*)d_in[1];   // int32! (jax x64-off downcast)
    float*       out = (float*)d_out;

    zero_kernel<<<(NROWS + 255) / 256, 256>>>();

    dim3 grid(NROWS / BN, NROWS / BM);      // 64 x 64; lower triangle early-exits
    sim_kernel<<<grid, NTHR>>>(X, T);

    lastrow_kernel<<<NROWS / 256, 256>>>(X, T);
    reduce_kernel<<<NROWS / 256, 256>>>();
    write_kernel<<<1, 32>>>(out);
}

// round 13
// speedup vs baseline: 3.5980x; 3.5980x over previous
#include <cuda_runtime.h>
#include <cuda_bf16.h>
#include <cstdint>

// ---------------------------------------------------------------------------
// LiftedStructureLoss  (N=8192, D=512, 128 classes)
// bf16 tensor-core GEMM (mma.sync.m16n8k16, fp32 accum) over upper-triangular
// 128x128 tiles; cp.async double-buffered smem pipeline; register-resident
// fused masked-exp epilogue. Last-row statistics byte-identical fp32.
// Targets are int32 (JAX x64-off downcast).
// ---------------------------------------------------------------------------

#define NROWS 8192
#define DIM   512
#define BM    128
#define BN    128
#define BK    32
#define SKA   40      // padded smem row stride in bf16 elems (80 B) -> conflict-free
#define NTHR  256
#define NIT   (DIM / BK)   // 16 k-stages

__device__ __align__(16) __nv_bfloat16 g_Xh[NROWS * DIM];   // bf16 copy of X
__device__ float g_pos[NROWS];
__device__ float g_neg[NROWS];
__device__ float g_last[4];   // [0]=pos_sim_sum [1]=neg_sim_sum [2]=pos_cnt [3]=neg_cnt
__device__ float g_red[2];    // [0]=loss_sum    [1]=skipped_row_count

// ---------------------------------------------------------------------------
__global__ void zero_kernel() {
    int i = blockIdx.x * blockDim.x + threadIdx.x;
    if (i < NROWS) { g_pos[i] = 0.f; g_neg[i] = 0.f; }
    if (i < 4) g_last[i] = 0.f;
    if (i < 2) g_red[i]  = 0.f;
}

// fp32 -> bf16 conversion of X (one float4 per thread)
__global__ void cvt_kernel(const float* __restrict__ X) {
    const int i = blockIdx.x * blockDim.x + threadIdx.x;   // float4 index
    const float4 v = ((const float4*)X)[i];
    __nv_bfloat162* o = (__nv_bfloat162*)g_Xh;
    o[2 * i]     = __floats2bfloat162_rn(v.x, v.y);
    o[2 * i + 1] = __floats2bfloat162_rn(v.z, v.w);
}

// ---------------------------------------------------------------------------
__device__ __forceinline__ void cpasync16(uint32_t dst, const void* src) {
    asm volatile("cp.async.ca.shared.global [%0], [%1], 16;\n"
                 :: "r"(dst), "l"(src));
}
__device__ __forceinline__ void cpasync_commit() {
    asm volatile("cp.async.commit_group;\n" ::: "memory");
}
template <int N>
__device__ __forceinline__ void cpasync_wait() {
    asm volatile("cp.async.wait_group %0;\n" :: "n"(N) : "memory");
}

// ---------------------------------------------------------------------------
// Main fused tensor-core GEMM + masked-exp epilogue, upper-triangular tiles.
// 8 warps as 2(M) x 4(N); warp tile 64x32; mma.m16n8k16 bf16 -> f32.
// cp.async 2-stage smem double buffer.
// ---------------------------------------------------------------------------
__global__ __launch_bounds__(NTHR, 2)
void sim_kernel(const int* __restrict__ T) {
    const int bi = blockIdx.y;
    const int bj = blockIdx.x;
    if (bj < bi) return;                       // upper triangle (incl. diagonal)

    __shared__ __align__(16) __nv_bfloat16 As[2][BM * SKA];  // [stage][row*SKA+k]
    __shared__ __align__(16) __nv_bfloat16 Bs[2][BN * SKA];
    __shared__ int   tr[BM], tc[BN];
    __shared__ float sPR[BM], sNR[BM], sPC[BN], sNC[BN];

    const int tid = threadIdx.x;
    if (tid < BM) {
        tr[tid]  = T[bi * BM + tid];
        tc[tid]  = T[bj * BN + tid];
        sPR[tid] = 0.f; sNR[tid] = 0.f; sPC[tid] = 0.f; sNC[tid] = 0.f;
    }

    const int lane = tid & 31;
    const int wid  = tid >> 5;
    const int wm   = wid >> 2;          // 0..1  (M position)
    const int wn   = wid & 3;           // 0..3  (N position)
    const int grp  = lane >> 2;         // 0..7
    const int tig  = lane & 3;          // 0..3

    float acc[4][4][4];
#pragma unroll
    for (int mf = 0; mf < 4; mf++)
#pragma unroll
        for (int nf = 0; nf < 4; nf++)
#pragma unroll
            for (int r = 0; r < 4; r++) acc[mf][nf][r] = 0.f;

    const __nv_bfloat16* Ag = g_Xh + (size_t)bi * BM * DIM;
    const __nv_bfloat16* Bg = g_Xh + (size_t)bj * BN * DIM;

    // Per k-stage each matrix needs 128 rows x 32 bf16 = 512 x 16B chunks.
    // 256 threads -> 2 chunks each: c0 = tid (rows 0..63), c1 = tid+256.
    const int r0 = tid >> 2,         q0 = tid & 3;
    const int r1 = (tid + 256) >> 2, q1 = (tid + 256) & 3;

    const uint32_t sA0 = (uint32_t)__cvta_generic_to_shared(&As[0][0]);
    const uint32_t sA1 = (uint32_t)__cvta_generic_to_shared(&As[1][0]);
    const uint32_t sB0 = (uint32_t)__cvta_generic_to_shared(&Bs[0][0]);
    const uint32_t sB1 = (uint32_t)__cvta_generic_to_shared(&Bs[1][0]);
    const uint32_t oA0 = (uint32_t)(r0 * SKA + q0 * 8) * 2;   // byte offsets
    const uint32_t oA1 = (uint32_t)(r1 * SKA + q1 * 8) * 2;

    // ---- prologue: fill stage 0 (k0 = 0)
    cpasync16(sA0 + oA0, Ag + r0 * DIM + q0 * 8);
    cpasync16(sA0 + oA1, Ag + r1 * DIM + q1 * 8);
    cpasync16(sB0 + oA0, Bg + r0 * DIM + q0 * 8);
    cpasync16(sB0 + oA1, Bg + r1 * DIM + q1 * 8);
    cpasync_commit();

    for (int it = 0; it < NIT; it++) {
        // kick off next stage
        if (it + 1 < NIT) {
            const int k0 = (it + 1) * BK;
            const uint32_t dA = ((it + 1) & 1) ? sA1 : sA0;
            const uint32_t dB = ((it + 1) & 1) ? sB1 : sB0;
            cpasync16(dA + oA0, Ag + r0 * DIM + k0 + q0 * 8);
            cpasync16(dA + oA1, Ag + r1 * DIM + k0 + q1 * 8);
            cpasync16(dB + oA0, Bg + r0 * DIM + k0 + q0 * 8);
            cpasync16(dB + oA1, Bg + r1 * DIM + k0 + q1 * 8);
            cpasync_commit();
            cpasync_wait<1>();       // current stage (it) complete
        } else {
            cpasync_wait<0>();
        }
        __syncthreads();

        const __nv_bfloat16* Ast = As[it & 1];
        const __nv_bfloat16* Bst = Bs[it & 1];

#pragma unroll
        for (int ko = 0; ko < 2; ko++) {        // two k16 steps per stage
            unsigned a[4][4], b[4][2];
            const __nv_bfloat16* ab = Ast + (wm * 64 + grp) * SKA + ko * 16 + 2 * tig;
#pragma unroll
            for (int mf = 0; mf < 4; mf++) {
                const __nv_bfloat16* p = ab + mf * 16 * SKA;
                a[mf][0] = *(const unsigned*)(p);
                a[mf][1] = *(const unsigned*)(p + 8 * SKA);
                a[mf][2] = *(const unsigned*)(p + 8);
                a[mf][3] = *(const unsigned*)(p + 8 * SKA + 8);
            }
            const __nv_bfloat16* bb = Bst + (wn * 32 + grp) * SKA + ko * 16 + 2 * tig;
#pragma unroll
            for (int nf = 0; nf < 4; nf++) {
                const __nv_bfloat16* p = bb + nf * 8 * SKA;
                b[nf][0] = *(const unsigned*)(p);
                b[nf][1] = *(const unsigned*)(p + 8);
            }
#pragma unroll
            for (int mf = 0; mf < 4; mf++)
#pragma unroll
                for (int nf = 0; nf < 4; nf++) {
                    asm volatile(
                        "mma.sync.aligned.m16n8k16.row.col.f32.bf16.bf16.f32 "
                        "{%0,%1,%2,%3}, {%4,%5,%6,%7}, {%8,%9}, {%0,%1,%2,%3};\n"
                        : "+f"(acc[mf][nf][0]), "+f"(acc[mf][nf][1]),
                          "+f"(acc[mf][nf][2]), "+f"(acc[mf][nf][3])
                        : "r"(a[mf][0]), "r"(a[mf][1]), "r"(a[mf][2]), "r"(a[mf][3]),
                          "r"(b[nf][0]), "r"(b[nf][1]));
                }
        }
        __syncthreads();   // stage (it) fully consumed before refill next iter
    }

    // ---- epilogue: masked exp, accumulate row sums (and col sums if off-diag)
    // element (mf,nf,j,i): row = wm*64+mf*16+grp+j*8, col = wn*32+nf*8+2*tig+i
    const bool offdiag = (bi != bj);
    float cP[4][2], cN[4][2];
#pragma unroll
    for (int nf = 0; nf < 4; nf++)
#pragma unroll
        for (int i = 0; i < 2; i++) { cP[nf][i] = 0.f; cN[nf][i] = 0.f; }

#pragma unroll
    for (int mf = 0; mf < 4; mf++)
#pragma unroll
        for (int j = 0; j < 2; j++) {
            const int rm = wm * 64 + mf * 16 + grp + j * 8;
            const int tRow = tr[rm];
            float rP = 0.f, rN = 0.f;
#pragma unroll
            for (int nf = 0; nf < 4; nf++)
#pragma unroll
                for (int i = 0; i < 2; i++) {
                    const int cn = wn * 32 + nf * 8 + 2 * tig + i;
                    const float s = acc[mf][nf][j * 2 + i];
                    if (tRow == tc[cn]) {
                        if (s < 1.0f) {              // drops (most) self-sims
                            const float e = __expf(1.0f - s);
                            rP += e; cP[nf][i] += e;
                        }
                    } else {
                        const float e = __expf(s);
                        rN += e; cN[nf][i] += e;
                    }
                }
            atomicAdd(&sPR[rm], rP);
            atomicAdd(&sNR[rm], rN);
        }
    if (offdiag) {
#pragma unroll
        for (int nf = 0; nf < 4; nf++)
#pragma unroll
            for (int i = 0; i < 2; i++) {
                const int cn = wn * 32 + nf * 8 + 2 * tig + i;
                atomicAdd(&sPC[cn], cP[nf][i]);
                atomicAdd(&sNC[cn], cN[nf][i]);
            }
    }
    __syncthreads();

    if (tid < BM) {
        atomicAdd(&g_pos[bi * BM + tid], sPR[tid]);
        atomicAdd(&g_neg[bi * BM + tid], sNR[tid]);
        if (offdiag) {
            atomicAdd(&g_pos[bj * BN + tid], sPC[tid]);
            atomicAdd(&g_neg[bj * BN + tid], sNC[tid]);
        }
    }
}

// ---------------------------------------------------------------------------
// Last-row statistics in plain fp32. The per-thread dot product (4-lane split
// accumulation) is byte-identical to the round-7 passing version — it decides
// the precision-critical sim[last,last] < 1.0 coin flip.
// ---------------------------------------------------------------------------
__global__ void lastrow_kernel(const float* __restrict__ X,
                               const int* __restrict__ T) {
    __shared__ float xl[DIM];
    __shared__ float red[4][8];
    const int tid = threadIdx.x;
    for (int i = tid; i < DIM; i += blockDim.x)
        xl[i] = X[(size_t)(NROWS - 1) * DIM + i];
    __syncthreads();

    const int j = blockIdx.x * blockDim.x + tid;

    const int tl = T[NROWS - 1];
    const float4* xr = (const float4*)(X + (size_t)j * DIM);
    const float4* xs = (const float4*)xl;
    float a0 = 0.f, a1 = 0.f, a2 = 0.f, a3 = 0.f;
#pragma unroll 8
    for (int k = 0; k < DIM / 4; k++) {
        const float4 v = xr[k];
        const float4 w = xs[k];
        a0 = fmaf(v.x, w.x, a0);
        a1 = fmaf(v.y, w.y, a1);
        a2 = fmaf(v.z, w.z, a2);
        a3 = fmaf(v.w, w.w, a3);
    }
    const float s = (a0 + a1) + (a2 + a3);

    float v0 = 0.f, v1 = 0.f, v2 = 0.f, v3 = 0.f;
    if (T[j] == tl) {
        if (s < 1.0f) { v0 = s; v2 = 1.f; }
    } else {
        v1 = s; v3 = 1.f;
    }
#pragma unroll
    for (int o = 16; o > 0; o >>= 1) {
        v0 += __shfl_down_sync(0xffffffffu, v0, o);
        v1 += __shfl_down_sync(0xffffffffu, v1, o);
        v2 += __shfl_down_sync(0xffffffffu, v2, o);
        v3 += __shfl_down_sync(0xffffffffu, v3, o);
    }
    const int lane = tid & 31, wrp = tid >> 5;
    if (lane == 0) { red[0][wrp] = v0; red[1][wrp] = v1; red[2][wrp] = v2; red[3][wrp] = v3; }
    __syncthreads();
    if (tid < 4) {
        float t = 0.f;
#pragma unroll
        for (int w = 0; w < 8; w++) t += red[tid][w];
        atomicAdd(&g_last[tid], t);
    }
}

// ---------------------------------------------------------------------------
__global__ void reduce_kernel() {
    __shared__ float red[2][8];
    const int i = blockIdx.x * blockDim.x + threadIdx.x;
    float v = 0.f, sk = 0.f;
    const float ns = g_neg[i];
    if (ns > 0.f) v = logf(g_pos[i]) + logf(ns);
    else          sk = 1.f;
#pragma unroll
    for (int o = 16; o > 0; o >>= 1) {
        v  += __shfl_down_sync(0xffffffffu, v, o);
        sk += __shfl_down_sync(0xffffffffu, sk, o);
    }
    const int lane = threadIdx.x & 31, wrp = threadIdx.x >> 5;
    if (lane == 0) { red[0][wrp] = v; red[1][wrp] = sk; }
    __syncthreads();
    if (threadIdx.x < 2) {
        float t = 0.f;
#pragma unroll
        for (int w = 0; w < 8; w++) t += red[threadIdx.x][w];
        atomicAdd(&g_red[threadIdx.x], t);
    }
}

__global__ void write_kernel(float* __restrict__ out) {
    if (threadIdx.x == 0) {
        out[0] = g_red[0] / (float)NROWS;   // loss
        out[1] = g_red[1] / (float)NROWS;   // prec (fraction of skipped rows)
        out[2] = g_last[0] / g_last[2];     // mean_pos_sim (last row)
        out[3] = g_last[1] / g_last[3];     // mean_neg_sim (last row)
    }
}

// ---------------------------------------------------------------------------
extern "C" void kernel_launch(void* const* d_in, const int* in_sizes, int n_in,
                              void* d_out, int out_size) {
    const float* X   = (const float*)d_in[0];
    const int*   T   = (const int*)d_in[1];   // int32! (jax x64-off downcast)
    float*       out = (float*)d_out;

    zero_kernel<<<(NROWS + 255) / 256, 256>>>();
    cvt_kernel<<<(NROWS * DIM / 4) / 256, 256>>>(X);

    dim3 grid(NROWS / BN, NROWS / BM);      // 64 x 64; lower triangle early-exits
    sim_kernel<<<grid, NTHR>>>(T);

    lastrow_kernel<<<NROWS / 256, 256>>>(X, T);
    reduce_kernel<<<NROWS / 256, 256>>>();
    write_kernel<<<1, 32>>>(out);
}

// round 15
// speedup vs baseline: 3.8288x; 1.0641x over previous
#include <cuda_runtime.h>
#include <cuda_bf16.h>
#include <cstdint>

// ---------------------------------------------------------------------------
// LiftedStructureLoss  (N=8192, D=512, 128 classes)
// bf16 tensor-core GEMM (mma.sync.m16n8k16, fp32 accum) over upper-triangular
// 128x128 tiles; cp.async double-buffered smem pipeline; ldmatrix fragment
// loads; register-resident fused masked-exp epilogue.
// Last-row statistics: 4-way row-split fp32, with the j=8191 (diagonal,
// coin-flip-critical) dot recomputed byte-identically to the round-7 kernel.
// Targets are int32 (JAX x64-off downcast).
// ---------------------------------------------------------------------------

#define NROWS 8192
#define DIM   512
#define BM    128
#define BN    128
#define BK    32
#define SKA   40      // padded smem row stride in bf16 elems (80 B) -> conflict-free
#define NTHR  256
#define NIT   (DIM / BK)   // 16 k-stages
#define STAGE_BYTES (BM * SKA * 2)   // 10240 B per matrix per stage

__device__ __align__(16) __nv_bfloat16 g_Xh[NROWS * DIM];   // bf16 copy of X
__device__ float g_pos[NROWS];
__device__ float g_neg[NROWS];
__device__ float g_last[4];   // [0]=pos_sim_sum [1]=neg_sim_sum [2]=pos_cnt [3]=neg_cnt
__device__ float g_red[2];    // [0]=loss_sum    [1]=skipped_row_count

// ---------------------------------------------------------------------------
__global__ void zero_kernel() {
    int i = blockIdx.x * blockDim.x + threadIdx.x;
    if (i < NROWS) { g_pos[i] = 0.f; g_neg[i] = 0.f; }
    if (i < 4) g_last[i] = 0.f;
    if (i < 2) g_red[i]  = 0.f;
}

// fp32 -> bf16 conversion of X (one float4 per thread)
__global__ void cvt_kernel(const float* __restrict__ X) {
    const int i = blockIdx.x * blockDim.x + threadIdx.x;   // float4 index
    const float4 v = ((const float4*)X)[i];
    __nv_bfloat162* o = (__nv_bfloat162*)g_Xh;
    o[2 * i]     = __floats2bfloat162_rn(v.x, v.y);
    o[2 * i + 1] = __floats2bfloat162_rn(v.z, v.w);
}

// ---------------------------------------------------------------------------
__device__ __forceinline__ void cpasync16(uint32_t dst, const void* src) {
    asm volatile("cp.async.ca.shared.global [%0], [%1], 16;\n"
                 :: "r"(dst), "l"(src));
}
__device__ __forceinline__ void cpasync_commit() {
    asm volatile("cp.async.commit_group;\n" ::: "memory");
}
template <int N>
__device__ __forceinline__ void cpasync_wait() {
    asm volatile("cp.async.wait_group %0;\n" :: "n"(N) : "memory");
}
__device__ __forceinline__ void ldsm4(unsigned& r0, unsigned& r1,
                                      unsigned& r2, unsigned& r3, uint32_t addr) {
    asm volatile("ldmatrix.sync.aligned.m8n8.x4.shared.b16 {%0,%1,%2,%3}, [%4];\n"
                 : "=r"(r0), "=r"(r1), "=r"(r2), "=r"(r3) : "r"(addr));
}

// ---------------------------------------------------------------------------
// Main fused tensor-core GEMM + masked-exp epilogue, upper-triangular tiles.
// 8 warps as 2(M) x 4(N); warp tile 64x32; mma.m16n8k16 bf16 -> f32.
// cp.async 2-stage smem double buffer; ldmatrix.x4 fragment loads.
// ---------------------------------------------------------------------------
__global__ __launch_bounds__(NTHR, 2)
void sim_kernel(const int* __restrict__ T) {
    const int bi = blockIdx.y;
    const int bj = blockIdx.x;
    if (bj < bi) return;                       // upper triangle (incl. diagonal)

    __shared__ __align__(16) __nv_bfloat16 As[2][BM * SKA];  // [stage][row*SKA+k]
    __shared__ __align__(16) __nv_bfloat16 Bs[2][BN * SKA];
    __shared__ int   tr[BM], tc[BN];
    __shared__ float sPR[BM], sNR[BM], sPC[BN], sNC[BN];

    const int tid = threadIdx.x;
    if (tid < BM) {
        tr[tid]  = T[bi * BM + tid];
        tc[tid]  = T[bj * BN + tid];
        sPR[tid] = 0.f; sNR[tid] = 0.f; sPC[tid] = 0.f; sNC[tid] = 0.f;
    }

    const int lane = tid & 31;
    const int wid  = tid >> 5;
    const int wm   = wid >> 2;          // 0..1  (M position)
    const int wn   = wid & 3;           // 0..3  (N position)
    const int grp  = lane >> 2;         // 0..7
    const int tig  = lane & 3;          // 0..3

    float acc[4][4][4];
#pragma unroll
    for (int mf = 0; mf < 4; mf++)
#pragma unroll
        for (int nf = 0; nf < 4; nf++)
#pragma unroll
            for (int r = 0; r < 4; r++) acc[mf][nf][r] = 0.f;

    const __nv_bfloat16* Ag = g_Xh + (size_t)bi * BM * DIM;
    const __nv_bfloat16* Bg = g_Xh + (size_t)bj * BN * DIM;

    // Per k-stage each matrix needs 128 rows x 32 bf16 = 512 x 16B chunks.
    const int r0 = tid >> 2,         q0 = tid & 3;
    const int r1 = (tid + 256) >> 2, q1 = (tid + 256) & 3;

    const uint32_t sA = (uint32_t)__cvta_generic_to_shared(&As[0][0]);
    const uint32_t sB = (uint32_t)__cvta_generic_to_shared(&Bs[0][0]);
    const uint32_t oA0 = (uint32_t)(r0 * SKA + q0 * 8) * 2;   // byte offsets
    const uint32_t oA1 = (uint32_t)(r1 * SKA + q1 * 8) * 2;

    // ldmatrix lane addresses (byte offsets within a stage):
    //   A[mf]: lines = rows wm*64+mf*16 + (lane&15), k-half = (lane>>4)&1
    //   B[pr]: lines = cols wn*32+pr*16 + (lane>>4)*8+(lane&7), k-half = (lane>>3)&1
    uint32_t aoff[4], boff[2];
    {
        const int l15 = lane & 15, ka = (lane >> 4) & 1;
#pragma unroll
        for (int mf = 0; mf < 4; mf++)
            aoff[mf] = (uint32_t)((wm * 64 + mf * 16 + l15) * SKA + ka * 8) * 2;
        const int colB = ((lane >> 4) << 3) + (lane & 7), kb = (lane >> 3) & 1;
#pragma unroll
        for (int pr = 0; pr < 2; pr++)
            boff[pr] = (uint32_t)((wn * 32 + pr * 16 + colB) * SKA + kb * 8) * 2;
    }

    // ---- prologue: fill stage 0 (k0 = 0)
    cpasync16(sA + oA0, Ag + r0 * DIM + q0 * 8);
    cpasync16(sA + oA1, Ag + r1 * DIM + q1 * 8);
    cpasync16(sB + oA0, Bg + r0 * DIM + q0 * 8);
    cpasync16(sB + oA1, Bg + r1 * DIM + q1 * 8);
    cpasync_commit();

    for (int it = 0; it < NIT; it++) {
        // kick off next stage
        if (it + 1 < NIT) {
            const int k0 = (it + 1) * BK;
            const uint32_t st = ((it + 1) & 1) ? STAGE_BYTES : 0;
            cpasync16(sA + st + oA0, Ag + r0 * DIM + k0 + q0 * 8);
            cpasync16(sA + st + oA1, Ag + r1 * DIM + k0 + q1 * 8);
            cpasync16(sB + st + oA0, Bg + r0 * DIM + k0 + q0 * 8);
            cpasync16(sB + st + oA1, Bg + r1 * DIM + k0 + q1 * 8);
            cpasync_commit();
            cpasync_wait<1>();       // current stage (it) complete
        } else {
            cpasync_wait<0>();
        }
        __syncthreads();

        const uint32_t st = (it & 1) ? STAGE_BYTES : 0;
        const uint32_t aBase = sA + st;
        const uint32_t bBase = sB + st;

#pragma unroll
        for (int ko = 0; ko < 2; ko++) {        // two k16 steps per stage
            unsigned a[4][4], b[4][2];
#pragma unroll
            for (int mf = 0; mf < 4; mf++)
                ldsm4(a[mf][0], a[mf][1], a[mf][2], a[mf][3],
                      aBase + aoff[mf] + ko * 32);
#pragma unroll
            for (int pr = 0; pr < 2; pr++)
                ldsm4(b[2 * pr][0], b[2 * pr][1], b[2 * pr + 1][0], b[2 * pr + 1][1],
                      bBase + boff[pr] + ko * 32);
#pragma unroll
            for (int mf = 0; mf < 4; mf++)
#pragma unroll
                for (int nf = 0; nf < 4; nf++) {
                    asm volatile(
                        "mma.sync.aligned.m16n8k16.row.col.f32.bf16.bf16.f32 "
                        "{%0,%1,%2,%3}, {%4,%5,%6,%7}, {%8,%9}, {%0,%1,%2,%3};\n"
                        : "+f"(acc[mf][nf][0]), "+f"(acc[mf][nf][1]),
                          "+f"(acc[mf][nf][2]), "+f"(acc[mf][nf][3])
                        : "r"(a[mf][0]), "r"(a[mf][1]), "r"(a[mf][2]), "r"(a[mf][3]),
                          "r"(b[nf][0]), "r"(b[nf][1]));
                }
        }
        __syncthreads();   // stage (it) fully consumed before refill next iter
    }

    // ---- epilogue: masked exp, accumulate row sums (and col sums if off-diag)
    // element (mf,nf,j,i): row = wm*64+mf*16+grp+j*8, col = wn*32+nf*8+2*tig+i
    const bool offdiag = (bi != bj);
    float cP[4][2], cN[4][2];
#pragma unroll
    for (int nf = 0; nf < 4; nf++)
#pragma unroll
        for (int i = 0; i < 2; i++) { cP[nf][i] = 0.f; cN[nf][i] = 0.f; }

#pragma unroll
    for (int mf = 0; mf < 4; mf++)
#pragma unroll
        for (int j = 0; j < 2; j++) {
            const int rm = wm * 64 + mf * 16 + grp + j * 8;
            const int tRow = tr[rm];
            float rP = 0.f, rN = 0.f;
#pragma unroll
            for (int nf = 0; nf < 4; nf++)
#pragma unroll
                for (int i = 0; i < 2; i++) {
                    const int cn = wn * 32 + nf * 8 + 2 * tig + i;
                    const float s = acc[mf][nf][j * 2 + i];
                    if (tRow == tc[cn]) {
                        if (s < 1.0f) {              // drops (most) self-sims
                            const float e = __expf(1.0f - s);
                            rP += e; cP[nf][i] += e;
                        }
                    } else {
                        const float e = __expf(s);
                        rN += e; cN[nf][i] += e;
                    }
                }
            atomicAdd(&sPR[rm], rP);
            atomicAdd(&sNR[rm], rN);
        }
    if (offdiag) {
#pragma unroll
        for (int nf = 0; nf < 4; nf++)
#pragma unroll
            for (int i = 0; i < 2; i++) {
                const int cn = wn * 32 + nf * 8 + 2 * tig + i;
                atomicAdd(&sPC[cn], cP[nf][i]);
                atomicAdd(&sNC[cn], cN[nf][i]);
            }
    }
    __syncthreads();

    if (tid < BM) {
        atomicAdd(&g_pos[bi * BM + tid], sPR[tid]);
        atomicAdd(&g_neg[bi * BM + tid], sNR[tid]);
        if (offdiag) {
            atomicAdd(&g_pos[bj * BN + tid], sPC[tid]);
            atomicAdd(&g_neg[bj * BN + tid], sNC[tid]);
        }
    }
}

// ---------------------------------------------------------------------------
// Last-row statistics, fp32. Each row split across 4 threads (128 dims each)
// for full-chip parallelism (128 CTAs). The only coin-flip-sensitive value is
// j = NROWS-1 (self-sim ~ 1.0; all other positive sims are far from 1.0), so
// that row's dot is recomputed with the byte-identical round-7 sequence.
// ---------------------------------------------------------------------------
__global__ void lastrow_kernel(const float* __restrict__ X,
                               const int* __restrict__ T) {
    __shared__ float xl[DIM];
    __shared__ float red[4];
    const int tid = threadIdx.x;
    for (int i = tid; i < DIM; i += blockDim.x)
        xl[i] = X[(size_t)(NROWS - 1) * DIM + i];
    if (tid < 4) red[tid] = 0.f;
    __syncthreads();

    const int gid  = blockIdx.x * blockDim.x + tid;
    const int j    = gid >> 2;          // row
    const int part = gid & 3;           // k-chunk (128 dims)

    const float4* xr = (const float4*)(X + (size_t)j * DIM) + part * 32;
    const float4* xs = (const float4*)xl + part * 32;
    float a0 = 0.f, a1 = 0.f, a2 = 0.f, a3 = 0.f;
#pragma unroll 8
    for (int k = 0; k < 32; k++) {
        const float4 v = xr[k];
        const float4 w = xs[k];
        a0 = fmaf(v.x, w.x, a0);
        a1 = fmaf(v.y, w.y, a1);
        a2 = fmaf(v.z, w.z, a2);
        a3 = fmaf(v.w, w.w, a3);
    }
    float s = (a0 + a1) + (a2 + a3);
    // combine the 4 chunk partials within the 4-lane group
    s += __shfl_down_sync(0xffffffffu, s, 2);
    s += __shfl_down_sync(0xffffffffu, s, 1);

    if (part == 0) {
        if (j == NROWS - 1) {
            // byte-identical round-7 dot (decides the s<1.0 diagonal coin flip)
            const float4* fr = (const float4*)(X + (size_t)(NROWS - 1) * DIM);
            const float4* fs = (const float4*)xl;
            float b0 = 0.f, b1 = 0.f, b2 = 0.f, b3 = 0.f;
#pragma unroll 8
            for (int k = 0; k < DIM / 4; k++) {
                const float4 v = fr[k];
                const float4 w = fs[k];
                b0 = fmaf(v.x, w.x, b0);
                b1 = fmaf(v.y, w.y, b1);
                b2 = fmaf(v.z, w.z, b2);
                b3 = fmaf(v.w, w.w, b3);
            }
            s = (b0 + b1) + (b2 + b3);
        }
        const int tl = T[NROWS - 1];
        if (T[j] == tl) {
            if (s < 1.0f) {
                atomicAdd(&red[0], s);
                atomicAdd(&red[2], 1.f);
            }
        } else {
            atomicAdd(&red[1], s);
            atomicAdd(&red[3], 1.f);
        }
    }
    __syncthreads();
    if (tid < 4 && red[tid] != 0.f) atomicAdd(&g_last[tid], red[tid]);
}

// ---------------------------------------------------------------------------
__global__ void reduce_kernel() {
    __shared__ float red[2][8];
    const int i = blockIdx.x * blockDim.x + threadIdx.x;
    float v = 0.f, sk = 0.f;
    const float ns = g_neg[i];
    if (ns > 0.f) v = logf(g_pos[i]) + logf(ns);
    else          sk = 1.f;
#pragma unroll
    for (int o = 16; o > 0; o >>= 1) {
        v  += __shfl_down_sync(0xffffffffu, v, o);
        sk += __shfl_down_sync(0xffffffffu, sk, o);
    }
    const int lane = threadIdx.x & 31, wrp = threadIdx.x >> 5;
    if (lane == 0) { red[0][wrp] = v; red[1][wrp] = sk; }
    __syncthreads();
    if (threadIdx.x < 2) {
        float t = 0.f;
#pragma unroll
        for (int w = 0; w < 8; w++) t += red[threadIdx.x][w];
        atomicAdd(&g_red[threadIdx.x], t);
    }
}

__global__ void write_kernel(float* __restrict__ out) {
    if (threadIdx.x == 0) {
        out[0] = g_red[0] / (float)NROWS;   // loss
        out[1] = g_red[1] / (float)NROWS;   // prec (fraction of skipped rows)
        out[2] = g_last[0] / g_last[2];     // mean_pos_sim (last row)
        out[3] = g_last[1] / g_last[3];     // mean_neg_sim (last row)
    }
}

// ---------------------------------------------------------------------------
extern "C" void kernel_launch(void* const* d_in, const int* in_sizes, int n_in,
                              void* d_out, int out_size) {
    const float* X   = (const float*)d_in[0];
    const int*   T   = (const int*)d_in[1];   // int32! (jax x64-off downcast)
    float*       out = (float*)d_out;

    zero_kernel<<<(NROWS + 255) / 256, 256>>>();
    cvt_kernel<<<(NROWS * DIM / 4) / 256, 256>>>(X);

    dim3 grid(NROWS / BN, NROWS / BM);      // 64 x 64; lower triangle early-exits
    sim_kernel<<<grid, NTHR>>>(T);

    lastrow_kernel<<<NROWS * 4 / 256, 256>>>(X, T);
    reduce_kernel<<<NROWS / 256, 256>>>();
    write_kernel<<<1, 32>>>(out);
}